// round 10
// baseline (speedup 1.0000x reference)
#include <cuda_runtime.h>
#include <math.h>

#define EPSV 1e-8f

typedef unsigned long long ull;

namespace {
constexpr int B  = 32;
constexpr int S  = 64;
constexpr int H  = 200;
constexpr int L  = 20;
constexpr int HP = 202;      // smem row stride (101 ull; 101%16=5 -> conflict-free)
constexpr int CS = 400;      // con_* inner stride (2*H)
constexpr int MV = 160;      // 8*L output columns
constexpr int PSIZE = B * S * MV;
constexpr int AST = 66;      // att/attT row stride in fused kernel
constexpr int WST = 200;     // match W2 row stride
}

// packed f32x2 helpers (ptxas never auto-fuses these)
__device__ __forceinline__ void fma2(ull& d, ull a, ull b) {
    asm("fma.rn.f32x2 %0, %1, %2, %0;" : "+l"(d) : "l"(a), "l"(b));
}
__device__ __forceinline__ ull mul2(ull a, ull b) {
    ull r; asm("mul.rn.f32x2 %0, %1, %2;" : "=l"(r) : "l"(a), "l"(b)); return r;
}
__device__ __forceinline__ float red2(ull v) {
    float2 f = *reinterpret_cast<float2*>(&v);
    return f.x + f.y;
}
__device__ __forceinline__ ull pack2(float x, float y) {
    float2 f; f.x = x; f.y = y;
    return *reinterpret_cast<ull*>(&f);
}

// ---------------- scratch (device globals; no allocation allowed) -------------
__device__ __align__(16) float g_amean_h[2 * B * S * H];
__device__ __align__(16) float g_amax_h [2 * B * S * H];
__device__ __align__(16) float g_amean_p[2 * B * S * H];
__device__ __align__(16) float g_amax_p [2 * B * S * H];

// =============== Kernel A: fused attention + att mean/max vectors ============
// grid (B, 2), 256 threads. Cosine att (4x4 tile GEMM), row/col sums, then the
// mean/max attention-weighted vectors for BOTH sides, all from smem.
__global__ void __launch_bounds__(256)
attnderiv_kernel(const float* __restrict__ con_p,
                 const float* __restrict__ con_h) {
    extern __shared__ float sm[];
    float* P     = sm;                 // S*HP  (raw p rows)
    float* Hm    = P  + S * HP;        // S*HP  (raw h rows)
    float* att   = Hm + S * HP;        // S*AST (att[p][q])
    float* attT  = att + S * AST;      // S*AST (att[q][p])
    float* np    = attT + S * AST;     // S
    float* nh    = np + S;             // S
    float* rsumS = nh + S;             // S
    float* csumS = rsumS + S;          // S
    float* redCS = csumS + S;          // S*8

    const int b = blockIdx.x, dir = blockIdx.y;
    const int tid = threadIdx.x;
    const float* pbase = con_p + (size_t)b * S * CS + dir * H;
    const float* hbase = con_h + (size_t)b * S * CS + dir * H;

    for (int i2 = tid; i2 < S * 100; i2 += 256) {
        int s = i2 / 100, h2 = i2 % 100;
        *reinterpret_cast<float2*>(P  + s * HP + 2 * h2) =
            *reinterpret_cast<const float2*>(pbase + s * CS + 2 * h2);
        *reinterpret_cast<float2*>(Hm + s * HP + 2 * h2) =
            *reinterpret_cast<const float2*>(hbase + s * CS + 2 * h2);
    }
    __syncthreads();

    if (tid < 64) {
        float acc = 0.f;
        #pragma unroll 4
        for (int k = 0; k < 100; k++) {
            float2 v = *reinterpret_cast<const float2*>(P + tid * HP + 2 * k);
            acc += v.x * v.x + v.y * v.y;
        }
        np[tid] = sqrtf(acc);
    } else if (tid < 128) {
        int q = tid - 64;
        float acc = 0.f;
        #pragma unroll 4
        for (int k = 0; k < 100; k++) {
            float2 v = *reinterpret_cast<const float2*>(Hm + q * HP + 2 * k);
            acc += v.x * v.x + v.y * v.y;
        }
        nh[q] = sqrtf(acc);
    }
    __syncthreads();

    // ---- att GEMM (4x4 tile, f32x2 packed) ----
    {
        const int tx = tid & 15, ty = tid >> 4;
        const int lane = tid & 31, warp = tid >> 5;
        const ull* Ap[4]; const ull* Bp[4];
        #pragma unroll
        for (int i = 0; i < 4; i++) Ap[i] = reinterpret_cast<const ull*>(P  + (ty + 16 * i) * HP);
        #pragma unroll
        for (int j = 0; j < 4; j++) Bp[j] = reinterpret_cast<const ull*>(Hm + (tx + 16 * j) * HP);

        ull acc2[4][4];
        #pragma unroll
        for (int i = 0; i < 4; i++)
            #pragma unroll
            for (int j = 0; j < 4; j++) acc2[i][j] = 0ull;

        ull ca[4], cb[4];
        #pragma unroll
        for (int i = 0; i < 4; i++) ca[i] = Ap[i][0];
        #pragma unroll
        for (int j = 0; j < 4; j++) cb[j] = Bp[j][0];

        #pragma unroll 2
        for (int h2 = 1; h2 < 100; h2++) {
            ull ta[4], tb[4];
            #pragma unroll
            for (int i = 0; i < 4; i++) ta[i] = Ap[i][h2];
            #pragma unroll
            for (int j = 0; j < 4; j++) tb[j] = Bp[j][h2];
            #pragma unroll
            for (int i = 0; i < 4; i++)
                #pragma unroll
                for (int j = 0; j < 4; j++) fma2(acc2[i][j], ca[i], cb[j]);
            #pragma unroll
            for (int i = 0; i < 4; i++) ca[i] = ta[i];
            #pragma unroll
            for (int j = 0; j < 4; j++) cb[j] = tb[j];
        }
        #pragma unroll
        for (int i = 0; i < 4; i++)
            #pragma unroll
            for (int j = 0; j < 4; j++) fma2(acc2[i][j], ca[i], cb[j]);

        float rsum[4], csum[4];
        #pragma unroll
        for (int i = 0; i < 4; i++) rsum[i] = 0.f;
        #pragma unroll
        for (int j = 0; j < 4; j++) csum[j] = 0.f;

        #pragma unroll
        for (int i = 0; i < 4; i++) {
            int p = ty + 16 * i;
            #pragma unroll
            for (int j = 0; j < 4; j++) {
                int q = tx + 16 * j;
                float d = np[p] * nh[q];
                float c = red2(acc2[i][j]) / (d > EPSV ? d : EPSV);
                att [p * AST + q] = c;
                attT[q * AST + p] = c;
                rsum[i] += c;
                csum[j] += c;
            }
        }
        #pragma unroll
        for (int m = 1; m <= 8; m <<= 1)
            #pragma unroll
            for (int i = 0; i < 4; i++)
                rsum[i] += __shfl_xor_sync(0xffffffffu, rsum[i], m);
        if (tx == 0) {
            #pragma unroll
            for (int i = 0; i < 4; i++)
                rsumS[ty + 16 * i] = rsum[i];
        }
        #pragma unroll
        for (int j = 0; j < 4; j++)
            csum[j] += __shfl_xor_sync(0xffffffffu, csum[j], 16);
        if (lane < 16) {
            #pragma unroll
            for (int j = 0; j < 4; j++)
                redCS[(tx + 16 * j) * 8 + warp] = csum[j];
        }
    }
    __syncthreads();
    if (tid < 64) {
        float s0 = 0.f;
        #pragma unroll
        for (int k = 0; k < 8; k++) s0 += redCS[tid * 8 + k];
        csumS[tid] = s0;
    }
    __syncthreads();

    // ---- deriv phase: mean/max over the att axis, both sides, from smem ----
    if (tid < 200) {
        const int oi = tid / 25, hi = tid % 25;
        const int o0 = oi * 8;

        for (int side = 0; side < 2; side++) {
            const float* M  = (side == 0) ? att : attT;   // M[o][*]
            const float* V  = (side == 0) ? Hm  : P;      // V[*][h], stride HP
            const float* ds = (side == 0) ? rsumS : csumS;
            float* gmean = (side == 0 ? g_amean_h : g_amean_p)
                         + (size_t)(dir * B + b) * S * H;
            float* gmax  = (side == 0 ? g_amax_h  : g_amax_p )
                         + (size_t)(dir * B + b) * S * H;

            for (int ck = 0; ck < 2; ck++) {
                const int hb = ck * 100 + hi * 4;

                float ss[8][4], sx[8][4];
                #pragma unroll
                for (int io = 0; io < 8; io++)
                    #pragma unroll
                    for (int k = 0; k < 4; k++) { ss[io][k] = 0.f; sx[io][k] = -INFINITY; }

                for (int q2 = 0; q2 < 32; q2++) {
                    const int q = 2 * q2;
                    float2 av[8];
                    #pragma unroll
                    for (int io = 0; io < 8; io++)
                        av[io] = *reinterpret_cast<const float2*>(M + (o0 + io) * AST + q);
                    float2 va0 = *reinterpret_cast<const float2*>(V + q * HP + hb);
                    float2 va1 = *reinterpret_cast<const float2*>(V + q * HP + hb + 2);
                    float2 vb0 = *reinterpret_cast<const float2*>(V + (q + 1) * HP + hb);
                    float2 vb1 = *reinterpret_cast<const float2*>(V + (q + 1) * HP + hb + 2);
                    float vv0[4] = {va0.x, va0.y, va1.x, va1.y};
                    float vv1[4] = {vb0.x, vb0.y, vb1.x, vb1.y};
                    #pragma unroll
                    for (int io = 0; io < 8; io++) {
                        float ax = av[io].x, ay = av[io].y;
                        #pragma unroll
                        for (int k = 0; k < 4; k++) {
                            float t0 = ax * vv0[k];
                            float t1 = ay * vv1[k];
                            ss[io][k] += t0 + t1;
                            sx[io][k] = fmaxf(sx[io][k], fmaxf(t0, t1));
                        }
                    }
                }
                #pragma unroll
                for (int io = 0; io < 8; io++) {
                    float d = ds[o0 + io];
                    float inv = 1.f / (d > EPSV ? d : EPSV);
                    float4 m4, x4;
                    m4.x = ss[io][0] * inv; m4.y = ss[io][1] * inv;
                    m4.z = ss[io][2] * inv; m4.w = ss[io][3] * inv;
                    x4.x = sx[io][0]; x4.y = sx[io][1]; x4.z = sx[io][2]; x4.w = sx[io][3];
                    *reinterpret_cast<float4*>(gmean + (o0 + io) * H + hb) = m4;
                    *reinterpret_cast<float4*>(gmax  + (o0 + io) * H + hb) = x4;
                }
            }
        }
    }
}

// ================== Kernel B1: "full" mp_match (kind 0) =====================
// grid (B, 4, 2). V1 rows via float4 gmem loads (L2-resident); v2 row + W^2 in
// smem. 5x float4 batches -> MLP ~5, half the L1 requests of ull loads.
__global__ void __launch_bounds__(128)
match_full_kernel(const float* __restrict__ con_p,
                  const float* __restrict__ con_h,
                  const float* __restrict__ w1, const float* __restrict__ w2,
                  float* __restrict__ out) {
    extern __shared__ float sm[];
    float* V2 = sm;                 // WST (single row)
    float* W2 = V2 + WST;           // L*WST

    const int b = blockIdx.x;
    const int side = blockIdx.y >> 1;
    const int dir = blockIdx.y & 1;
    const int shalf = blockIdx.z;
    const int tid = threadIdx.x;
    const int s0 = shalf * 32;

    const float* v2 = (side == 0 ? con_h : con_p)
                    + (size_t)b * S * CS + (dir == 0 ? (S - 1) : 0) * CS + dir * H;
    for (int h2 = tid; h2 < 100; h2 += 128)
        *reinterpret_cast<float2*>(V2 + 2 * h2) =
            *reinterpret_cast<const float2*>(v2 + 2 * h2);

    const float* w = (dir == 0 ? w1 : w2);
    for (int i2 = tid; i2 < L * 100; i2 += 128) {
        int l = i2 / 100, h2 = i2 % 100;
        float2 wv = *reinterpret_cast<const float2*>(w + l * H + 2 * h2);
        float2 sq; sq.x = wv.x * wv.x; sq.y = wv.y * wv.y;
        *reinterpret_cast<float2*>(W2 + l * WST + 2 * h2) = sq;
    }
    __syncthreads();

    const int tx = tid & 3;        // l group: l = tx*5 + il
    const int ty = tid >> 2;       // s = s0 + ty

    const float* v1 = (side == 0 ? con_p : con_h)
                    + (size_t)b * S * CS + (size_t)(s0 + ty) * CS + dir * H;
    const float4* A4 = reinterpret_cast<const float4*>(v1);
    const float4* B4 = reinterpret_cast<const float4*>(V2);
    const ull* Wp[5];
    #pragma unroll
    for (int il = 0; il < 5; il++)
        Wp[il] = reinterpret_cast<const ull*>(W2 + (tx * 5 + il) * WST);

    ull dacc[5], naa[5], nbb[5];
    #pragma unroll
    for (int il = 0; il < 5; il++) { dacc[il] = 0ull; naa[il] = 0ull; nbb[il] = 0ull; }

    #pragma unroll 1
    for (int i4 = 0; i4 < 50; i4 += 5) {
        float4 a4[5], b4[5];
        #pragma unroll
        for (int u = 0; u < 5; u++) a4[u] = A4[i4 + u];
        #pragma unroll
        for (int u = 0; u < 5; u++) b4[u] = B4[i4 + u];
        #pragma unroll
        for (int u = 0; u < 5; u++) {
            ull a0 = pack2(a4[u].x, a4[u].y), a1 = pack2(a4[u].z, a4[u].w);
            ull b0 = pack2(b4[u].x, b4[u].y), b1 = pack2(b4[u].z, b4[u].w);
            const int h2 = 2 * (i4 + u);
            ull u10 = mul2(a0, b0), u20 = mul2(a0, a0), u30 = mul2(b0, b0);
            ull u11 = mul2(a1, b1), u21 = mul2(a1, a1), u31 = mul2(b1, b1);
            #pragma unroll
            for (int il = 0; il < 5; il++) {
                ull wv0 = Wp[il][h2], wv1 = Wp[il][h2 + 1];
                fma2(dacc[il], u10, wv0);
                fma2(naa[il], u20, wv0);
                fma2(nbb[il], u30, wv0);
                fma2(dacc[il], u11, wv1);
                fma2(naa[il], u21, wv1);
                fma2(nbb[il], u31, wv1);
            }
        }
    }

    const int col = dir * 80;
    float* obase = out + (size_t)side * PSIZE + (size_t)b * S * MV;
    #pragma unroll
    for (int il = 0; il < 5; il++) {
        float d = sqrtf(red2(naa[il])) * sqrtf(red2(nbb[il]));
        obase[(s0 + ty) * MV + col + (tx * 5 + il)] = red2(dacc[il]) / fmaxf(d, EPSV);
    }
}

// ================ Kernel B2: att mean/max mp_match (kinds 1,2) ===============
// grid (B, 8, 2). V1/V2 rows via float4 gmem loads (L2-resident), batched x5
// per side (MLP 10); only W^2 staged in smem (16KB).
__global__ void __launch_bounds__(128)
match_att_kernel(const float* __restrict__ con_p,
                 const float* __restrict__ con_h,
                 const float* __restrict__ w5, const float* __restrict__ w6,
                 const float* __restrict__ w7, const float* __restrict__ w8,
                 float* __restrict__ out) {
    extern __shared__ float sm[];
    float* W2 = sm;                 // L*WST

    const int b = blockIdx.x;
    const int side = blockIdx.y >> 2;
    const int kind = 1 + ((blockIdx.y >> 1) & 1);
    const int dir = blockIdx.y & 1;
    const int shalf = blockIdx.z;
    const int tid = threadIdx.x;
    const int s0 = shalf * 32;

    const float* w = (kind == 1 ? (dir == 0 ? w5 : w6) : (dir == 0 ? w7 : w8));
    for (int i2 = tid; i2 < L * 100; i2 += 128) {
        int l = i2 / 100, h2 = i2 % 100;
        float2 wv = *reinterpret_cast<const float2*>(w + l * H + 2 * h2);
        float2 sq; sq.x = wv.x * wv.x; sq.y = wv.y * wv.y;
        *reinterpret_cast<float2*>(W2 + l * WST + 2 * h2) = sq;
    }
    __syncthreads();

    const int tx = tid & 3;
    const int ty = tid >> 2;
    const int s = s0 + ty;

    const float* v1 = (side == 0 ? con_p : con_h)
                    + (size_t)b * S * CS + (size_t)s * CS + dir * H;
    const float* v2 = (kind == 1 ? (side == 0 ? g_amean_h : g_amean_p)
                                 : (side == 0 ? g_amax_h  : g_amax_p))
                    + (size_t)(dir * B + b) * S * H + (size_t)s * H;
    const float4* A4 = reinterpret_cast<const float4*>(v1);
    const float4* B4 = reinterpret_cast<const float4*>(v2);
    const ull* Wp[5];
    #pragma unroll
    for (int il = 0; il < 5; il++)
        Wp[il] = reinterpret_cast<const ull*>(W2 + (tx * 5 + il) * WST);

    ull dacc[5], naa[5], nbb[5];
    #pragma unroll
    for (int il = 0; il < 5; il++) { dacc[il] = 0ull; naa[il] = 0ull; nbb[il] = 0ull; }

    #pragma unroll 1
    for (int i4 = 0; i4 < 50; i4 += 5) {
        float4 a4[5], b4[5];
        #pragma unroll
        for (int u = 0; u < 5; u++) a4[u] = A4[i4 + u];
        #pragma unroll
        for (int u = 0; u < 5; u++) b4[u] = B4[i4 + u];
        #pragma unroll
        for (int u = 0; u < 5; u++) {
            ull a0 = pack2(a4[u].x, a4[u].y), a1 = pack2(a4[u].z, a4[u].w);
            ull b0 = pack2(b4[u].x, b4[u].y), b1 = pack2(b4[u].z, b4[u].w);
            const int h2 = 2 * (i4 + u);
            ull u10 = mul2(a0, b0), u20 = mul2(a0, a0), u30 = mul2(b0, b0);
            ull u11 = mul2(a1, b1), u21 = mul2(a1, a1), u31 = mul2(b1, b1);
            #pragma unroll
            for (int il = 0; il < 5; il++) {
                ull wv0 = Wp[il][h2], wv1 = Wp[il][h2 + 1];
                fma2(dacc[il], u10, wv0);
                fma2(naa[il], u20, wv0);
                fma2(nbb[il], u30, wv0);
                fma2(dacc[il], u11, wv1);
                fma2(naa[il], u21, wv1);
                fma2(nbb[il], u31, wv1);
            }
        }
    }

    const int col = (kind == 1 ? 40 : 60) + dir * 80;
    float* obase = out + (size_t)side * PSIZE + (size_t)b * S * MV;
    #pragma unroll
    for (int il = 0; il < 5; il++) {
        float d = sqrtf(red2(naa[il])) * sqrtf(red2(nbb[il]));
        obase[s * MV + col + (tx * 5 + il)] = red2(dacc[il]) / fmaxf(d, EPSV);
    }
}

// ================= Kernel C: pairwise mp + max reductions ====================
// grid (B, 10, 2): one block per (b, l-pair, dir). 256 threads, 4x4 (p,q) tile,
// RAW P/H in smem (l-independent) + per-l w^2 broadcast: D_l = sum w^2 * p * h.
__global__ void __launch_bounds__(256, 2)
pairwise_kernel(const float* __restrict__ con_p,
                const float* __restrict__ con_h,
                const float* __restrict__ w3,
                const float* __restrict__ w4,
                float* __restrict__ out) {
    extern __shared__ float sm[];
    float* P    = sm;                 // S*HP (raw p rows)
    float* Hm   = P  + S * HP;        // S*HP (raw h rows)
    float* W2   = Hm + S * HP;        // 2*HP (w^2 for the 2 perspectives)
    float* na   = W2 + 2 * HP;        // 2*S
    float* nb   = na + 2 * S;         // 2*S
    float* redQ = nb + 2 * S;         // 2*S*8

    const int b = blockIdx.x, lg = blockIdx.y, dir = blockIdx.z;
    const int l0 = lg * 2;
    const int tid = threadIdx.x;

    const float* w = (dir == 0 ? w3 : w4) + l0 * H;
    for (int i2 = tid; i2 < 2 * 100; i2 += 256) {
        int lr = i2 / 100, h2 = i2 % 100;
        float2 wv = *reinterpret_cast<const float2*>(w + lr * H + 2 * h2);
        float2 sq; sq.x = wv.x * wv.x; sq.y = wv.y * wv.y;
        *reinterpret_cast<float2*>(W2 + lr * HP + 2 * h2) = sq;
    }

    const float* pb = con_p + (size_t)b * S * CS + dir * H;
    const float* hb = con_h + (size_t)b * S * CS + dir * H;
    for (int i2 = tid; i2 < S * 100; i2 += 256) {
        int s = i2 / 100, h2 = i2 % 100;
        *reinterpret_cast<float2*>(P  + s * HP + 2 * h2) =
            *reinterpret_cast<const float2*>(pb + s * CS + 2 * h2);
        *reinterpret_cast<float2*>(Hm + s * HP + 2 * h2) =
            *reinterpret_cast<const float2*>(hb + s * CS + 2 * h2);
    }
    __syncthreads();

    // norms: 128 threads -> (row, lr) for a-side, 128 for b-side
    {
        int t = tid & 127;
        int row = t >> 1, lr = t & 1;
        const float* src = (tid < 128) ? (P + row * HP) : (Hm + row * HP);
        const float* wr  = W2 + lr * HP;
        float acc = 0.f;
        #pragma unroll 4
        for (int k = 0; k < 100; k++) {
            float2 v = *reinterpret_cast<const float2*>(src + 2 * k);
            float2 q = *reinterpret_cast<const float2*>(wr + 2 * k);
            acc += q.x * v.x * v.x + q.y * v.y * v.y;
        }
        if (tid < 128) na[lr * S + row] = sqrtf(acc);
        else           nb[lr * S + row] = sqrtf(acc);
    }
    __syncthreads();

    const int tx = tid & 15, ty = tid >> 4;
    const int lane = tid & 31, warp = tid >> 5;
    const ull* Ap[4]; const ull* Bp[4];
    #pragma unroll
    for (int i = 0; i < 4; i++) Ap[i] = reinterpret_cast<const ull*>(P  + (ty + 16 * i) * HP);
    #pragma unroll
    for (int j = 0; j < 4; j++) Bp[j] = reinterpret_cast<const ull*>(Hm + (tx + 16 * j) * HP);
    const ull* W0 = reinterpret_cast<const ull*>(W2);
    const ull* W1 = reinterpret_cast<const ull*>(W2 + HP);

    ull acc2[2][4][4];
    #pragma unroll
    for (int lr = 0; lr < 2; lr++)
        #pragma unroll
        for (int i = 0; i < 4; i++)
            #pragma unroll
            for (int j = 0; j < 4; j++) acc2[lr][i][j] = 0ull;

    #pragma unroll 2
    for (int h2 = 0; h2 < 100; h2++) {
        ull pa[4], hbv[4];
        #pragma unroll
        for (int i = 0; i < 4; i++) pa[i] = Ap[i][h2];
        #pragma unroll
        for (int j = 0; j < 4; j++) hbv[j] = Bp[j][h2];
        ull w20 = W0[h2], w21 = W1[h2];
        ull sa[4];
        #pragma unroll
        for (int i = 0; i < 4; i++) sa[i] = mul2(pa[i], w20);
        #pragma unroll
        for (int i = 0; i < 4; i++)
            #pragma unroll
            for (int j = 0; j < 4; j++) fma2(acc2[0][i][j], sa[i], hbv[j]);
        #pragma unroll
        for (int i = 0; i < 4; i++) sa[i] = mul2(pa[i], w21);
        #pragma unroll
        for (int i = 0; i < 4; i++)
            #pragma unroll
            for (int j = 0; j < 4; j++) fma2(acc2[1][i][j], sa[i], hbv[j]);
    }

    #pragma unroll
    for (int lr = 0; lr < 2; lr++) {
        float pmax[4], qmax[4];
        #pragma unroll
        for (int i = 0; i < 4; i++) pmax[i] = -INFINITY;
        #pragma unroll
        for (int j = 0; j < 4; j++) qmax[j] = -INFINITY;

        #pragma unroll
        for (int i = 0; i < 4; i++) {
            int p = ty + 16 * i;
            #pragma unroll
            for (int j = 0; j < 4; j++) {
                int q = tx + 16 * j;
                float d = na[lr * S + p] * nb[lr * S + q];
                float c = red2(acc2[lr][i][j]) / (d > EPSV ? d : EPSV);
                pmax[i] = fmaxf(pmax[i], c);
                qmax[j] = fmaxf(qmax[j], c);
            }
        }
        const int colbase = (dir == 0 ? 20 : 100) + l0 + lr;
        #pragma unroll
        for (int m = 1; m <= 8; m <<= 1)
            #pragma unroll
            for (int i = 0; i < 4; i++)
                pmax[i] = fmaxf(pmax[i], __shfl_xor_sync(0xffffffffu, pmax[i], m));
        if (tx == 0) {
            #pragma unroll
            for (int i = 0; i < 4; i++)
                out[((size_t)b * S + (ty + 16 * i)) * MV + colbase] = pmax[i]; // mv_p
        }
        #pragma unroll
        for (int j = 0; j < 4; j++)
            qmax[j] = fmaxf(qmax[j], __shfl_xor_sync(0xffffffffu, qmax[j], 16));
        if (lane < 16) {
            #pragma unroll
            for (int j = 0; j < 4; j++)
                redQ[(lr * S + tx + 16 * j) * 8 + warp] = qmax[j];
        }
    }
    __syncthreads();
    if (tid < 128) {
        int lr = tid >> 6, q = tid & 63;
        float m = -INFINITY;
        #pragma unroll
        for (int k = 0; k < 8; k++) m = fmaxf(m, redQ[(lr * S + q) * 8 + k]);
        const int colbase = (dir == 0 ? 20 : 100) + l0 + lr;
        out[(size_t)PSIZE + ((size_t)b * S + q) * MV + colbase] = m;          // mv_h
    }
}

// ================================ launcher ===================================
extern "C" void kernel_launch(void* const* d_in, const int* in_sizes, int n_in,
                              void* d_out, int out_size) {
    const float* con_p = (const float*)d_in[0];
    const float* con_h = (const float*)d_in[1];
    const float* w1 = (const float*)d_in[2];
    const float* w2 = (const float*)d_in[3];
    const float* w3 = (const float*)d_in[4];
    const float* w4 = (const float*)d_in[5];
    const float* w5 = (const float*)d_in[6];
    const float* w6 = (const float*)d_in[7];
    const float* w7 = (const float*)d_in[8];
    const float* w8 = (const float*)d_in[9];
    float* out = (float*)d_out;

    constexpr size_t SM_AD = (size_t)(2 * S * HP + 2 * S * AST + 4 * S + S * 8) * sizeof(float);
    constexpr size_t SM_BF = (size_t)(WST + L * WST) * sizeof(float);
    constexpr size_t SM_BA = (size_t)(L * WST) * sizeof(float);
    constexpr size_t SM_C  = (size_t)(2 * S * HP + 2 * HP + 4 * S + 2 * S * 8) * sizeof(float);

    static cudaStream_t s2 = nullptr;
    static cudaEvent_t evFork = nullptr, evJoin = nullptr;
    static bool init_done = false;
    if (!init_done) {
        cudaFuncSetAttribute(attnderiv_kernel,  cudaFuncAttributeMaxDynamicSharedMemorySize, (int)SM_AD);
        cudaFuncSetAttribute(match_full_kernel, cudaFuncAttributeMaxDynamicSharedMemorySize, (int)SM_BF);
        cudaFuncSetAttribute(match_att_kernel,  cudaFuncAttributeMaxDynamicSharedMemorySize, (int)SM_BA);
        cudaFuncSetAttribute(pairwise_kernel,   cudaFuncAttributeMaxDynamicSharedMemorySize, (int)SM_C);
        cudaStreamCreateWithFlags(&s2, cudaStreamNonBlocking);
        cudaEventCreateWithFlags(&evFork, cudaEventDisableTiming);
        cudaEventCreateWithFlags(&evJoin, cudaEventDisableTiming);
        init_done = true;
    }

    // s2: pairwise alone (out cols 20-39/100-119).
    // stream 0: attnderiv -> match_att (cols 40-79/120-159) -> match_full
    // (cols 0-19/80-99). Branches are ~balanced.
    cudaEventRecord(evFork, 0);
    cudaStreamWaitEvent(s2, evFork, 0);
    pairwise_kernel<<<dim3(B, 10, 2), 256, SM_C, s2>>>(con_p, con_h, w3, w4, out);

    attnderiv_kernel<<<dim3(B, 2), 256, SM_AD>>>(con_p, con_h);
    match_att_kernel<<<dim3(B, 8, 2), 128, SM_BA>>>(con_p, con_h, w5, w6, w7, w8, out);
    match_full_kernel<<<dim3(B, 4, 2), 128, SM_BF>>>(con_p, con_h, w1, w2, out);

    cudaEventRecord(evJoin, s2);
    cudaStreamWaitEvent(0, evJoin, 0);
}